// round 9
// baseline (speedup 1.0000x reference)
#include <cuda_runtime.h>
#include <math.h>

#define H_IN   192
#define W_IN   192
#define HOUT   96
#define WOUT   96
#define C1     32
#define NN     17
#define BATCH  128

// Block: 32x16 output px = 16x8 Winograd tiles (2x2 px each); 512 threads
#define NTHR   512
#define BX     32
#define BY     16
#define NTX    16
#define NTY    8
#define NTILE  (NTX*NTY)   // 128

// h tile: 18 x 34, stride 36
#define HROWS  18
#define HCOLS  34
#define HSTR2  36
#define SMH    (HROWS*HSTR2)      // 648 floats per channel

// input tile: 37 x 69, stride 72
#define ITSY   37
#define ITSX   69
#define ISTR   72
#define NPOS   (HROWS*HCOLS)      // 612

#define SM_W1T (C1*12)            // 384
#define SM_IN  (ITSY*ISTR)        // 2664
#define SM_H   (C1*SMH)           // 20736
#define SM_U   (C1*NN*16)         // 8704
#define SM_FLOATS (SM_W1T + SM_IN + SM_H + SM_U)
#define SM_BYTES  (SM_FLOATS * 4)   // 129,952 B
// M staging (reuses s_h + s_U): 128 tiles * 9 * 20 = 23040 <= 29440 floats

__constant__ float cB1[C1];
__constant__ float cB2[NN];

__device__ float g_cms[(size_t)BATCH*NN*HOUT*WOUT];

// ---------- output chunk emitter ----------
template<int NB, int CH>
static __device__ __forceinline__ void emit_chunk(
    const float (&M)[NN][4], float* M_s, int t, int g, int tid,
    int b, int x0, int y0)
{
    #pragma unroll
    for (int nl = 0; nl < CH; nl++) {
        const int n = NB + nl;
        *(float4*)(M_s + (t*CH + nl)*20 + 4*g) =
            make_float4(M[n][0], M[n][1], M[n][2], M[n][3]);
    }
    __syncthreads();

    for (int i = tid; i < NTILE*CH; i += NTHR) {
        const int t2 = i & (NTILE-1);
        const int nl = i >> 7;
        const int n  = NB + nl;
        const float* mp = M_s + (t2*CH + nl)*20;
        const float4 m0 = *(const float4*)(mp);
        const float4 m1 = *(const float4*)(mp + 4);
        const float4 m2 = *(const float4*)(mp + 8);
        const float4 m3 = *(const float4*)(mp + 12);

        // Z = A^T M ; Y = Z A
        const float z00 = m0.x + m1.x + m2.x;
        const float z01 = m0.y + m1.y + m2.y;
        const float z02 = m0.z + m1.z + m2.z;
        const float z03 = m0.w + m1.w + m2.w;
        const float z10 = m1.x - m2.x - m3.x;
        const float z11 = m1.y - m2.y - m3.y;
        const float z12 = m1.z - m2.z - m3.z;
        const float z13 = m1.w - m2.w - m3.w;
        const float bb = cB2[n];
        const float y00 = z00 + z01 + z02 + bb;
        const float y01 = z01 - z02 - z03 + bb;
        const float y10 = z10 + z11 + z12 + bb;
        const float y11 = z11 - z12 - z13 + bb;

        const int ty_t = t2 >> 4, tx_t = t2 & 15;
        const int gy = y0 + 2*ty_t, gx = x0 + 2*tx_t;
        float* o = g_cms + ((size_t)(b*NN + n)*HOUT + gy)*WOUT + gx;
        *(float2*)o          = make_float2(y00, y01);
        *(float2*)(o + WOUT) = make_float2(y10, y11);
    }
    __syncthreads();
}

__global__ __launch_bounds__(NTHR, 1)
void conv_winograd_kernel(const float* __restrict__ crops,
                          const float* __restrict__ W1g,
                          const float* __restrict__ W2g)
{
    extern __shared__ float sm[];
    float* s_w1t = sm;                 // [C1][12]
    float* s_in  = sm + SM_W1T;        // [ITSY][ISTR]
    float* s_h   = s_in + SM_IN;       // [C1][HROWS][HSTR2]
    float* s_U   = s_h + SM_H;         // [C1*NN][16]

    const int tid = threadIdx.x;
    const int x0  = blockIdx.x * BX;
    const int y0  = blockIdx.y * BY;
    const int b   = blockIdx.z;

    // ---- stage transposed W1 ----
    for (int i = tid; i < 9*C1; i += NTHR) {
        int k = i / C1, c = i - k*C1;
        s_w1t[c*12 + k] = W1g[i];
    }
    // ---- stage input tile ----
    const float* img = crops + (size_t)b * H_IN * W_IN;
    for (int i = tid; i < ITSY*ITSX; i += NTHR) {
        int r  = i / ITSX, cc = i - r*ITSX;
        int iy = 2*y0 - 2 + r;
        int ix = 2*x0 - 2 + cc;
        float v = 0.f;
        if (iy >= 0 && iy < H_IN && ix >= 0 && ix < W_IN) v = img[iy*W_IN + ix];
        s_in[r*ISTR + cc] = v;
    }
    // ---- precompute U = G g G^T per (c,n) ----
    for (int i = tid; i < C1*NN; i += NTHR) {
        const int c = i / NN, n = i - c*NN;
        float gr[3][3];
        #pragma unroll
        for (int r = 0; r < 3; r++)
            #pragma unroll
            for (int s = 0; s < 3; s++)
                gr[r][s] = W2g[((r*3 + s)*C1 + c)*NN + n];
        float T[4][3];
        #pragma unroll
        for (int s = 0; s < 3; s++) {
            const float t02 = gr[0][s] + gr[2][s];
            T[0][s] = gr[0][s];
            T[1][s] = 0.5f*(t02 + gr[1][s]);
            T[2][s] = 0.5f*(t02 - gr[1][s]);
            T[3][s] = gr[2][s];
        }
        float* up = s_U + i*16;
        #pragma unroll
        for (int r = 0; r < 4; r++) {
            const float u02 = T[r][0] + T[r][2];
            *(float4*)(up + 4*r) = make_float4(
                T[r][0], 0.5f*(u02 + T[r][1]), 0.5f*(u02 - T[r][1]), T[r][2]);
        }
    }
    __syncthreads();

    // ---- conv1: all 32 channels -> s_h (zero outside [0,96)) ----
    float in9[2][9];
    int   offh[2];
    bool  pmask[2], pborder[2];
    #pragma unroll
    for (int i = 0; i < 2; i++) {
        const int p = tid + i*NTHR;
        pmask[i] = (p < NPOS);
        const int pp = pmask[i] ? p : 0;
        const int ly = pp / HCOLS - 1;
        const int lx = pp - (pp / HCOLS)*HCOLS - 1;
        offh[i] = (ly+1)*HSTR2 + (lx+1);
        const int gy = y0 + ly, gx = x0 + lx;
        pborder[i] = (gy >= 0) & (gy < HOUT) & (gx >= 0) & (gx < WOUT);
        const float* r0 = s_in + (2*ly + 2)*ISTR + (2*lx + 2);
        #pragma unroll
        for (int ky = 0; ky < 3; ky++) {
            const float2 v2 = *(const float2*)(r0 + ky*ISTR);
            in9[i][ky*3+0] = v2.x;
            in9[i][ky*3+1] = v2.y;
            in9[i][ky*3+2] = r0[ky*ISTR + 2];
        }
    }
    #pragma unroll 1
    for (int c = 0; c < C1; c++) {
        const float4 wa = *(const float4*)(s_w1t + c*12);
        const float4 wb = *(const float4*)(s_w1t + c*12 + 4);
        const float  w8 = s_w1t[c*12 + 8];
        const float  b1c = cB1[c];
        float* hc = s_h + c*SMH;
        #pragma unroll
        for (int i = 0; i < 2; i++) {
            if (!pmask[i]) continue;
            float a = b1c;
            a = fmaf(in9[i][0], wa.x, a);
            a = fmaf(in9[i][1], wa.y, a);
            a = fmaf(in9[i][2], wa.z, a);
            a = fmaf(in9[i][3], wa.w, a);
            a = fmaf(in9[i][4], wb.x, a);
            a = fmaf(in9[i][5], wb.y, a);
            a = fmaf(in9[i][6], wb.z, a);
            a = fmaf(in9[i][7], wb.w, a);
            a = fmaf(in9[i][8], w8,   a);
            a = fmaxf(a, 0.f);
            hc[offh[i]] = pborder[i] ? a : 0.f;
        }
    }
    __syncthreads();

    // ---- conv2 Winograd: thread = (tile t, V-row g) ----
    const int g = tid & 3;
    const int t = tid >> 2;            // 0..127
    const int tx_t = t & 15;
    const int ty_t = t >> 4;

    int rA, rB; float sgn;
    if      (g == 0) { rA = 0; rB = 2; sgn = -1.f; }
    else if (g == 1) { rA = 1; rB = 2; sgn =  1.f; }
    else if (g == 2) { rA = 2; rB = 1; sgn = -1.f; }
    else             { rA = 1; rB = 3; sgn = -1.f; }
    const int rowA = (2*ty_t + rA)*HSTR2 + 2*tx_t;
    const int rowB = (2*ty_t + rB)*HSTR2 + 2*tx_t;

    float M[NN][4];
    #pragma unroll
    for (int n = 0; n < NN; n++) {
        M[n][0]=0.f; M[n][1]=0.f; M[n][2]=0.f; M[n][3]=0.f;
    }

    #pragma unroll 1
    for (int c = 0; c < C1; c++) {
        const float* hc = s_h + c*SMH;
        const float2 a0 = *(const float2*)(hc + rowA);      // 8B aligned
        const float2 a1 = *(const float2*)(hc + rowA + 2);
        const float2 b0 = *(const float2*)(hc + rowB);
        const float2 b1 = *(const float2*)(hc + rowB + 2);

        const float W0 = fmaf(sgn, b0.x, a0.x);
        const float W1 = fmaf(sgn, b0.y, a0.y);
        const float W2 = fmaf(sgn, b1.x, a1.x);
        const float W3 = fmaf(sgn, b1.y, a1.y);

        const float V0 = W0 - W2, V1 = W1 + W2, V2 = W2 - W1, V3 = W1 - W3;

        const float4* up = (const float4*)(s_U + c*NN*16) + g;
        #pragma unroll
        for (int n = 0; n < NN; n++) {
            const float4 u = up[n*4];
            M[n][0] = fmaf(u.x, V0, M[n][0]);
            M[n][1] = fmaf(u.y, V1, M[n][1]);
            M[n][2] = fmaf(u.z, V2, M[n][2]);
            M[n][3] = fmaf(u.w, V3, M[n][3]);
        }
    }
    __syncthreads();   // s_h/s_U dead; M_s reuses them

    // ---- output transform in 2 static n-chunks ----
    float* M_s = s_h;                  // up to 29440 floats available
    emit_chunk<0, 9>(M, M_s, t, g, tid, b, x0, y0);
    emit_chunk<9, 8>(M, M_s, t, g, tid, b, x0, y0);
}

// one block per (b, n): argmax (first-index ties) + quarter-pixel refine + threshold + x2
__global__ void peaks_kernel(float* __restrict__ out)
{
    const int bn = blockIdx.x;
    const float* cm = g_cms + (size_t)bn * HOUT * WOUT;
    const int tid = threadIdx.x;

    float best = -INFINITY;
    int bidx = 0;
    for (int i = tid; i < HOUT*WOUT; i += 256) {
        float v = cm[i];
        if (v > best) { best = v; bidx = i; }
    }

    __shared__ float sv[256];
    __shared__ int   si[256];
    sv[tid] = best; si[tid] = bidx;
    __syncthreads();
    for (int s = 128; s > 0; s >>= 1) {
        if (tid < s) {
            float ov = sv[tid + s]; int oi = si[tid + s];
            if (ov > sv[tid] || (ov == sv[tid] && oi < si[tid])) {
                sv[tid] = ov; si[tid] = oi;
            }
        }
        __syncthreads();
    }

    if (tid == 0) {
        float val = sv[0];
        int idx = si[0];
        int yi = idx / WOUT;
        int xi = idx - yi * WOUT;

        int xm = max(xi-1, 0), xp = min(xi+1, WOUT-1);
        int ym = max(yi-1, 0), yp = min(yi+1, HOUT-1);
        float ddx = cm[yi*WOUT + xp] - cm[yi*WOUT + xm];
        float ddy = cm[yp*WOUT + xi] - cm[ym*WOUT + xi];
        float sx = (ddx > 0.f) ? 1.f : ((ddx < 0.f) ? -1.f : 0.f);
        float sy = (ddy > 0.f) ? 1.f : ((ddy < 0.f) ? -1.f : 0.f);

        float px = ((float)xi + 0.25f*sx) * 2.0f;
        float py = ((float)yi + 0.25f*sy) * 2.0f;
        if (!(val >= 0.2f)) { px = nanf(""); py = nanf(""); }

        out[bn*3 + 0] = px;
        out[bn*3 + 1] = py;
        out[bn*3 + 2] = val;
    }
}

extern "C" void kernel_launch(void* const* d_in, const int* in_sizes, int n_in,
                              void* d_out, int out_size)
{
    const float* crops = (const float*)d_in[0];
    const float* W1    = (const float*)d_in[1];
    const float* b1    = (const float*)d_in[2];
    const float* W2    = (const float*)d_in[3];
    const float* b2    = (const float*)d_in[4];
    float* out = (float*)d_out;

    cudaMemcpyToSymbolAsync(cB1, b1, C1*sizeof(float), 0, cudaMemcpyDeviceToDevice, 0);
    cudaMemcpyToSymbolAsync(cB2, b2, NN*sizeof(float), 0, cudaMemcpyDeviceToDevice, 0);

    cudaFuncSetAttribute(conv_winograd_kernel,
                         cudaFuncAttributeMaxDynamicSharedMemorySize, SM_BYTES);

    dim3 grid(WOUT/BX, HOUT/BY, BATCH);   // 3 x 6 x 128
    conv_winograd_kernel<<<grid, NTHR, SM_BYTES>>>(crops, W1, W2);

    peaks_kernel<<<BATCH*NN, 256>>>(out);
}

// round 10
// speedup vs baseline: 1.3674x; 1.3674x over previous
#include <cuda_runtime.h>
#include <math.h>

#define H_IN   192
#define W_IN   192
#define HOUT   96
#define WOUT   96
#define C1     32
#define NN     17
#define BATCH  128

// Block: 32x16 output px = 16x8 Winograd tiles (2x2 px each); 512 threads
// Mapping: g = tid>>7 (warp-uniform!), tile t = tid&127
#define NTHR   512
#define BX     32
#define BY     16
#define NTX    16
#define NTY    8
#define NTILE  (NTX*NTY)   // 128

// h tile: 18 x 34, stride 36
#define HROWS  18
#define HCOLS  34
#define HSTR2  36
#define SMH    (HROWS*HSTR2)      // 648 floats per channel

// input tile: 37 x 69, stride 72
#define ITSY   37
#define ITSX   69
#define ISTR   72
#define NPOS   (HROWS*HCOLS)      // 612

#define SM_W1T (C1*12)            // 384
#define SM_IN  (ITSY*ISTR)        // 2664
#define SM_H   (C1*SMH)           // 20736
#define SM_U   (4*C1*NN*4)        // 8704  ([g][c][n][4])
#define SM_FLOATS (SM_W1T + SM_IN + SM_H + SM_U)
#define SM_BYTES  (SM_FLOATS * 4)   // 129,952 B
// M staging (reuses s_h + s_U): 128 * 9 * 20 = 23040 <= 29440 floats

__constant__ float cB1[C1];
__constant__ float cB2[NN];

__device__ float g_cms[(size_t)BATCH*NN*HOUT*WOUT];

// ---------- output chunk emitter ----------
template<int NB, int CH>
static __device__ __forceinline__ void emit_chunk(
    const float (&M)[NN][4], float* M_s, int t, int g, int tid,
    int b, int x0, int y0)
{
    #pragma unroll
    for (int nl = 0; nl < CH; nl++) {
        const int n = NB + nl;
        *(float4*)(M_s + (t*CH + nl)*20 + 4*g) =
            make_float4(M[n][0], M[n][1], M[n][2], M[n][3]);
    }
    __syncthreads();

    for (int i = tid; i < NTILE*CH; i += NTHR) {
        const int t2 = i & (NTILE-1);
        const int nl = i >> 7;
        const int n  = NB + nl;
        const float* mp = M_s + (t2*CH + nl)*20;
        const float4 m0 = *(const float4*)(mp);
        const float4 m1 = *(const float4*)(mp + 4);
        const float4 m2 = *(const float4*)(mp + 8);
        const float4 m3 = *(const float4*)(mp + 12);

        // Z = A^T M ; Y = Z A
        const float z00 = m0.x + m1.x + m2.x;
        const float z01 = m0.y + m1.y + m2.y;
        const float z02 = m0.z + m1.z + m2.z;
        const float z03 = m0.w + m1.w + m2.w;
        const float z10 = m1.x - m2.x - m3.x;
        const float z11 = m1.y - m2.y - m3.y;
        const float z12 = m1.z - m2.z - m3.z;
        const float z13 = m1.w - m2.w - m3.w;
        const float bb = cB2[n];
        const float y00 = z00 + z01 + z02 + bb;
        const float y01 = z01 - z02 - z03 + bb;
        const float y10 = z10 + z11 + z12 + bb;
        const float y11 = z11 - z12 - z13 + bb;

        const int ty_t = t2 >> 4, tx_t = t2 & 15;
        const int gy = y0 + 2*ty_t, gx = x0 + 2*tx_t;
        float* o = g_cms + ((size_t)(b*NN + n)*HOUT + gy)*WOUT + gx;
        *(float2*)o          = make_float2(y00, y01);
        *(float2*)(o + WOUT) = make_float2(y10, y11);
    }
    __syncthreads();
}

__global__ __launch_bounds__(NTHR, 1)
void conv_winograd_kernel(const float* __restrict__ crops,
                          const float* __restrict__ W1g,
                          const float* __restrict__ W2g)
{
    extern __shared__ float sm[];
    float* s_w1t = sm;                 // [C1][12]
    float* s_in  = sm + SM_W1T;        // [ITSY][ISTR]
    float* s_h   = s_in + SM_IN;       // [C1][HROWS][HSTR2]
    float* s_U   = s_h + SM_H;         // [g][C1][NN][4]

    const int tid = threadIdx.x;
    const int x0  = blockIdx.x * BX;
    const int y0  = blockIdx.y * BY;
    const int b   = blockIdx.z;

    // ---- stage transposed W1 ----
    for (int i = tid; i < 9*C1; i += NTHR) {
        int k = i / C1, c = i - k*C1;
        s_w1t[c*12 + k] = W1g[i];
    }
    // ---- stage input tile ----
    const float* img = crops + (size_t)b * H_IN * W_IN;
    for (int i = tid; i < ITSY*ITSX; i += NTHR) {
        int r  = i / ITSX, cc = i - r*ITSX;
        int iy = 2*y0 - 2 + r;
        int ix = 2*x0 - 2 + cc;
        float v = 0.f;
        if (iy >= 0 && iy < H_IN && ix >= 0 && ix < W_IN) v = img[iy*W_IN + ix];
        s_in[r*ISTR + cc] = v;
    }
    // ---- precompute U = G w G^T, layout [g][c][n][4] ----
    for (int i = tid; i < C1*NN; i += NTHR) {
        const int c = i / NN, n = i - c*NN;
        float gr[3][3];
        #pragma unroll
        for (int r = 0; r < 3; r++)
            #pragma unroll
            for (int s = 0; s < 3; s++)
                gr[r][s] = W2g[((r*3 + s)*C1 + c)*NN + n];
        float T[4][3];
        #pragma unroll
        for (int s = 0; s < 3; s++) {
            const float t02 = gr[0][s] + gr[2][s];
            T[0][s] = gr[0][s];
            T[1][s] = 0.5f*(t02 + gr[1][s]);
            T[2][s] = 0.5f*(t02 - gr[1][s]);
            T[3][s] = gr[2][s];
        }
        #pragma unroll
        for (int r = 0; r < 4; r++) {
            const float u02 = T[r][0] + T[r][2];
            *(float4*)(s_U + ((r*C1 + c)*NN + n)*4) = make_float4(
                T[r][0], 0.5f*(u02 + T[r][1]), 0.5f*(u02 - T[r][1]), T[r][2]);
        }
    }
    __syncthreads();

    // ---- conv1: all 32 channels -> s_h (zero outside [0,96)) ----
    float in9[2][9];
    int   offh[2];
    bool  pmask[2], pborder[2];
    #pragma unroll
    for (int i = 0; i < 2; i++) {
        const int p = tid + i*NTHR;
        pmask[i] = (p < NPOS);
        const int pp = pmask[i] ? p : 0;
        const int ly = pp / HCOLS - 1;
        const int lx = pp - (pp / HCOLS)*HCOLS - 1;
        offh[i] = (ly+1)*HSTR2 + (lx+1);
        const int gy = y0 + ly, gx = x0 + lx;
        pborder[i] = (gy >= 0) & (gy < HOUT) & (gx >= 0) & (gx < WOUT);
        const float* r0 = s_in + (2*ly + 2)*ISTR + (2*lx + 2);
        #pragma unroll
        for (int ky = 0; ky < 3; ky++) {
            const float2 v2 = *(const float2*)(r0 + ky*ISTR);
            in9[i][ky*3+0] = v2.x;
            in9[i][ky*3+1] = v2.y;
            in9[i][ky*3+2] = r0[ky*ISTR + 2];
        }
    }
    #pragma unroll 1
    for (int c = 0; c < C1; c++) {
        const float4 wa = *(const float4*)(s_w1t + c*12);
        const float4 wb = *(const float4*)(s_w1t + c*12 + 4);
        const float  w8 = s_w1t[c*12 + 8];
        const float  b1c = cB1[c];
        float* hc = s_h + c*SMH;
        #pragma unroll
        for (int i = 0; i < 2; i++) {
            if (!pmask[i]) continue;
            float a = b1c;
            a = fmaf(in9[i][0], wa.x, a);
            a = fmaf(in9[i][1], wa.y, a);
            a = fmaf(in9[i][2], wa.z, a);
            a = fmaf(in9[i][3], wa.w, a);
            a = fmaf(in9[i][4], wb.x, a);
            a = fmaf(in9[i][5], wb.y, a);
            a = fmaf(in9[i][6], wb.z, a);
            a = fmaf(in9[i][7], wb.w, a);
            a = fmaf(in9[i][8], w8,   a);
            a = fmaxf(a, 0.f);
            hc[offh[i]] = pborder[i] ? a : 0.f;
        }
    }
    __syncthreads();

    // ---- conv2 Winograd: g warp-uniform, lane = tile ----
    const int g = tid >> 7;            // 0..3, same for all lanes of a warp
    const int t = tid & 127;           // tile 0..127
    const int tx_t = t & 15;
    const int ty_t = t >> 4;

    // warp-uniform B^T row combo for this g
    int rA, rB; float sgn;
    if      (g == 0) { rA = 0; rB = 2; sgn = -1.f; }
    else if (g == 1) { rA = 1; rB = 2; sgn =  1.f; }
    else if (g == 2) { rA = 2; rB = 1; sgn = -1.f; }
    else             { rA = 1; rB = 3; sgn = -1.f; }
    const int rowA = (2*ty_t + rA)*HSTR2 + 2*tx_t;
    const int rowB = (2*ty_t + rB)*HSTR2 + 2*tx_t;
    const float4* ug = (const float4*)(s_U + g*C1*NN*4);   // [c][n] float4s

    float M[NN][4];
    #pragma unroll
    for (int n = 0; n < NN; n++) {
        M[n][0]=0.f; M[n][1]=0.f; M[n][2]=0.f; M[n][3]=0.f;
    }

    #pragma unroll 1
    for (int c = 0; c < C1; c++) {
        const float* hc = s_h + c*SMH;
        const float2 a0 = *(const float2*)(hc + rowA);
        const float2 a1 = *(const float2*)(hc + rowA + 2);
        const float2 b0 = *(const float2*)(hc + rowB);
        const float2 b1 = *(const float2*)(hc + rowB + 2);

        const float W0 = fmaf(sgn, b0.x, a0.x);
        const float W1 = fmaf(sgn, b0.y, a0.y);
        const float W2 = fmaf(sgn, b1.x, a1.x);
        const float W3 = fmaf(sgn, b1.y, a1.y);

        const float V0 = W0 - W2, V1 = W1 + W2, V2 = W2 - W1, V3 = W1 - W3;

        const float4* up = ug + c*NN;      // broadcast: all lanes same address
        #pragma unroll
        for (int n = 0; n < NN; n++) {
            const float4 u = up[n];
            M[n][0] = fmaf(u.x, V0, M[n][0]);
            M[n][1] = fmaf(u.y, V1, M[n][1]);
            M[n][2] = fmaf(u.z, V2, M[n][2]);
            M[n][3] = fmaf(u.w, V3, M[n][3]);
        }
    }
    __syncthreads();   // s_h/s_U dead; M_s reuses them

    // ---- output transform in 2 static n-chunks ----
    float* M_s = s_h;
    emit_chunk<0, 9>(M, M_s, t, g, tid, b, x0, y0);
    emit_chunk<9, 8>(M, M_s, t, g, tid, b, x0, y0);
}

// one block per (b, n): argmax (first-index ties) + quarter-pixel refine + threshold + x2
__global__ void peaks_kernel(float* __restrict__ out)
{
    const int bn = blockIdx.x;
    const float* cm = g_cms + (size_t)bn * HOUT * WOUT;
    const int tid = threadIdx.x;

    float best = -INFINITY;
    int bidx = 0;
    for (int i = tid; i < HOUT*WOUT; i += 256) {
        float v = cm[i];
        if (v > best) { best = v; bidx = i; }
    }

    __shared__ float sv[256];
    __shared__ int   si[256];
    sv[tid] = best; si[tid] = bidx;
    __syncthreads();
    for (int s = 128; s > 0; s >>= 1) {
        if (tid < s) {
            float ov = sv[tid + s]; int oi = si[tid + s];
            if (ov > sv[tid] || (ov == sv[tid] && oi < si[tid])) {
                sv[tid] = ov; si[tid] = oi;
            }
        }
        __syncthreads();
    }

    if (tid == 0) {
        float val = sv[0];
        int idx = si[0];
        int yi = idx / WOUT;
        int xi = idx - yi * WOUT;

        int xm = max(xi-1, 0), xp = min(xi+1, WOUT-1);
        int ym = max(yi-1, 0), yp = min(yi+1, HOUT-1);
        float ddx = cm[yi*WOUT + xp] - cm[yi*WOUT + xm];
        float ddy = cm[yp*WOUT + xi] - cm[ym*WOUT + xi];
        float sx = (ddx > 0.f) ? 1.f : ((ddx < 0.f) ? -1.f : 0.f);
        float sy = (ddy > 0.f) ? 1.f : ((ddy < 0.f) ? -1.f : 0.f);

        float px = ((float)xi + 0.25f*sx) * 2.0f;
        float py = ((float)yi + 0.25f*sy) * 2.0f;
        if (!(val >= 0.2f)) { px = nanf(""); py = nanf(""); }

        out[bn*3 + 0] = px;
        out[bn*3 + 1] = py;
        out[bn*3 + 2] = val;
    }
}

extern "C" void kernel_launch(void* const* d_in, const int* in_sizes, int n_in,
                              void* d_out, int out_size)
{
    const float* crops = (const float*)d_in[0];
    const float* W1    = (const float*)d_in[1];
    const float* b1    = (const float*)d_in[2];
    const float* W2    = (const float*)d_in[3];
    const float* b2    = (const float*)d_in[4];
    float* out = (float*)d_out;

    cudaMemcpyToSymbolAsync(cB1, b1, C1*sizeof(float), 0, cudaMemcpyDeviceToDevice, 0);
    cudaMemcpyToSymbolAsync(cB2, b2, NN*sizeof(float), 0, cudaMemcpyDeviceToDevice, 0);

    cudaFuncSetAttribute(conv_winograd_kernel,
                         cudaFuncAttributeMaxDynamicSharedMemorySize, SM_BYTES);

    dim3 grid(WOUT/BX, HOUT/BY, BATCH);   // 3 x 6 x 128
    conv_winograd_kernel<<<grid, NTHR, SM_BYTES>>>(crops, W1, W2);

    peaks_kernel<<<BATCH*NN, 256>>>(out);
}